// round 14
// baseline (speedup 1.0000x reference)
#include <cuda_runtime.h>
#include <cuda_fp16.h>
#include <cstdint>
#include <cstddef>
#include <math.h>

#define NB    8192
#define DIN   1024
#define HID   2048
#define DOUT  1024
#define NE    8
#define GHID  1024
#define NSLOT (NB * 2)

// ------------------------- device scratch (static) -------------------------
__device__ float  g_h1[(size_t)NB * GHID];
__device__ __half g_xh[(size_t)NB * DIN];
__device__ __half g_xl[(size_t)NB * DIN];
__device__ __half g_gwh[(size_t)GHID * DIN];
__device__ __half g_gwl[(size_t)GHID * DIN];
__device__ __half g_Xg[(size_t)NSLOT * DIN];
__device__ __half g_H [(size_t)NSLOT * HID];
__device__ __half g_P [(size_t)NSLOT * HID];
__device__ __half g_O [(size_t)NSLOT * HID];
__device__ float  g_Y [(size_t)NSLOT * DOUT];
__device__ __half g_w1t[(size_t)NE * DIN * HID];
__device__ __half g_wpt[(size_t)NE * DIN * HID];
__device__ __half g_w2t[(size_t)NE * HID * HID];
__device__ __half g_w3t[(size_t)NE * HID * DOUT];
__device__ int   g_topk_e[NSLOT];
__device__ float g_topk_w[NSLOT];
__device__ int   g_token_slot[NSLOT];
__device__ int   g_slot_token[NSLOT];
__device__ int   g_counts[NE];
__device__ int   g_offsets[NE + 1];
__device__ int   g_cursor[NE];

// ------------------------------ helpers ------------------------------------
__device__ __forceinline__ uint32_t smem_u32(const void* p) {
    uint32_t a;
    asm("{ .reg .u64 t; cvta.to.shared.u64 t, %1; cvt.u32.u64 %0, t; }" : "=r"(a) : "l"(p));
    return a;
}
__device__ __forceinline__ uint32_t swz(uint32_t o) { return o ^ ((o >> 3) & 0x70); }

#define LDSM4(r0, r1, r2, r3, addr) \
    asm volatile("ldmatrix.sync.aligned.m8n8.x4.shared.b16 {%0,%1,%2,%3}, [%4];" \
                 : "=r"(r0), "=r"(r1), "=r"(r2), "=r"(r3) : "r"(addr))

#define MMA16(c, a, b0, b1) \
    asm volatile("mma.sync.aligned.m16n8k16.row.col.f32.f16.f16.f32 " \
                 "{%0,%1,%2,%3}, {%4,%5,%6,%7}, {%8,%9}, {%0,%1,%2,%3};" \
                 : "+f"((c)[0]), "+f"((c)[1]), "+f"((c)[2]), "+f"((c)[3]) \
                 : "r"((a)[0]), "r"((a)[1]), "r"((a)[2]), "r"((a)[3]), "r"(b0), "r"(b1))

#define CPA(dst, src, zf) \
    asm volatile("cp.async.cg.shared.global [%0], [%1], 16, %2;" :: "r"(dst), "l"(src), "r"(zf))
#define CPCOMMIT() asm volatile("cp.async.commit_group;")
#define CPWAIT(n)  asm volatile("cp.async.wait_group %0;" :: "n"(n))

// -------- weight transpose float[K][N] -> half[N][K], 64K x 32N tiles -------
template <bool SPLIT>
__global__ void __launch_bounds__(256) k_t16(
    const float* __restrict__ in, __half* __restrict__ oh, __half* __restrict__ ol,
    int K, int N) {
    __shared__ float t[64][33];
    size_t eo = (size_t)blockIdx.z * K * N;
    int k0 = blockIdx.y * 64, n0 = blockIdx.x * 32;
#pragma unroll
    for (int i = 0; i < 8; i++) {
        int idx = threadIdx.x + i * 256;
        int k = idx >> 5, n = idx & 31;
        t[k][n] = in[eo + (size_t)(k0 + k) * N + n0 + n];
    }
    __syncthreads();
#pragma unroll
    for (int i = 0; i < 4; i++) {
        int idx = threadIdx.x + i * 256;
        int n = idx >> 5, kk = idx & 31;
        float v0 = t[2 * kk][n], v1 = t[2 * kk + 1][n];
        __half h0 = __float2half_rn(v0), h1 = __float2half_rn(v1);
        size_t oi = eo + (size_t)(n0 + n) * K + k0 + 2 * kk;
        *(__half2*)(oh + oi) = __halves2half2(h0, h1);
        if (SPLIT)
            *(__half2*)(ol + oi) = __halves2half2(
                __float2half_rn(v0 - __half2float(h0)),
                __float2half_rn(v1 - __half2float(h1)));
    }
}

// ------------------------------ x hi/lo split -------------------------------
__global__ void __launch_bounds__(256) k_split_x(const float* __restrict__ x) {
    size_t i = (size_t)blockIdx.x * 256 + threadIdx.x;
    float4 v = ((const float4*)x)[i];
    __half hx = __float2half_rn(v.x), hy = __float2half_rn(v.y);
    __half hz = __float2half_rn(v.z), hw = __float2half_rn(v.w);
    ((__half2*)g_xh)[2 * i]     = __halves2half2(hx, hy);
    ((__half2*)g_xh)[2 * i + 1] = __halves2half2(hz, hw);
    ((__half2*)g_xl)[2 * i] = __halves2half2(
        __float2half_rn(v.x - __half2float(hx)), __float2half_rn(v.y - __half2float(hy)));
    ((__half2*)g_xl)[2 * i + 1] = __halves2half2(
        __float2half_rn(v.z - __half2float(hz)), __float2half_rn(v.w - __half2float(hw)));
}

// ------- gating GEMM: fp16 split, 3 products, 2-stage, BN=64, occ-2 --------
__global__ void __launch_bounds__(256, 2) k_gate16(const float* __restrict__ gb1) {
    const int K = DIN;
    int m0 = blockIdx.y * 128, n0 = blockIdx.x * 64;
    extern __shared__ char sm_raw[];
    uint32_t sb = (smem_u32(sm_raw) + 1023u) & ~1023u;
    int tid = threadIdx.x, warp = tid >> 5, lane = tid & 31;
    int wm = (warp & 1) * 64, wn = (warp >> 1) * 16;

    int lrow[4], lch[4], brow[2], bch[2];
#pragma unroll
    for (int i = 0; i < 4; i++) { int idx = tid + i * 256; lrow[i] = idx >> 3; lch[i] = idx & 7; }
#pragma unroll
    for (int i = 0; i < 2; i++) { int idx = tid + i * 256; brow[i] = idx >> 3; bch[i] = idx & 7; }

    float c[4][2][4];
#pragma unroll
    for (int a = 0; a < 4; a++)
#pragma unroll
        for (int b = 0; b < 2; b++)
#pragma unroll
            for (int q = 0; q < 4; q++) c[a][b][q] = 0.f;

    const int nk = K >> 6;
    auto issue = [&](int kt, int s) {
        uint32_t st = sb + (uint32_t)s * 49152;
#pragma unroll
        for (int i = 0; i < 4; i++) {
            int r = lrow[i];
            uint32_t so = swz((uint32_t)(r * 128 + lch[i] * 16));
            size_t go = (size_t)(m0 + r) * K + kt * 64 + lch[i] * 8;
            CPA(st + so,         (const char*)(g_xh + go), 16);
            CPA(st + 16384 + so, (const char*)(g_xl + go), 16);
        }
#pragma unroll
        for (int i = 0; i < 2; i++) {
            int r = brow[i];
            uint32_t so = swz((uint32_t)(r * 128 + bch[i] * 16));
            size_t gw = (size_t)(n0 + r) * K + kt * 64 + bch[i] * 8;
            CPA(st + 32768 + so, (const char*)(g_gwh + gw), 16);
            CPA(st + 40960 + so, (const char*)(g_gwl + gw), 16);
        }
    };
    issue(0, 0); CPCOMMIT();
    for (int kt = 0; kt < nk; kt++) {
        int s = kt & 1;
        if (kt + 1 < nk) { issue(kt + 1, s ^ 1); CPCOMMIT(); CPWAIT(1); }
        else CPWAIT(0);
        __syncthreads();
        uint32_t ah = sb + (uint32_t)s * 49152, al = ah + 16384, bh = ah + 32768, bl = ah + 40960;
#pragma unroll
        for (int ks = 0; ks < 4; ks++) {
            uint32_t A[4][4], L[4][4], BH[2][2], BL[2][2];
#pragma unroll
            for (int mi = 0; mi < 4; mi++) {
                uint32_t o = swz((uint32_t)((wm + mi * 16 + (lane & 15)) * 128 + ks * 32 + (lane >> 4) * 16));
                LDSM4(A[mi][0], A[mi][1], A[mi][2], A[mi][3], ah + o);
                LDSM4(L[mi][0], L[mi][1], L[mi][2], L[mi][3], al + o);
            }
            {
                uint32_t o = swz((uint32_t)((wn + (lane & 15)) * 128 + ks * 32 + (lane >> 4) * 16));
                uint32_t r0, r1, r2, r3;
                LDSM4(r0, r1, r2, r3, bh + o);
                BH[0][0] = r0; BH[0][1] = r2; BH[1][0] = r1; BH[1][1] = r3;
                LDSM4(r0, r1, r2, r3, bl + o);
                BL[0][0] = r0; BL[0][1] = r2; BL[1][0] = r1; BL[1][1] = r3;
            }
#pragma unroll
            for (int mi = 0; mi < 4; mi++)
#pragma unroll
                for (int ni = 0; ni < 2; ni++) {
                    MMA16(c[mi][ni], A[mi], BH[ni][0], BH[ni][1]);
                    MMA16(c[mi][ni], L[mi], BH[ni][0], BH[ni][1]);
                    MMA16(c[mi][ni], A[mi], BL[ni][0], BL[ni][1]);
                }
        }
        __syncthreads();
    }
#pragma unroll
    for (int mi = 0; mi < 4; mi++)
#pragma unroll
        for (int ni = 0; ni < 2; ni++) {
            int col = n0 + wn + ni * 8 + (lane & 3) * 2;
            float b0 = gb1[col], b1v = gb1[col + 1];
#pragma unroll
            for (int h = 0; h < 2; h++) {
                int r = m0 + wm + mi * 16 + (lane >> 2) + h * 8;
                *(float2*)(g_h1 + (size_t)r * GHID + col) =
                    make_float2(fmaxf(c[mi][ni][2 * h] + b0, 0.f),
                                fmaxf(c[mi][ni][2 * h + 1] + b1v, 0.f));
            }
        }
}

// ---------------- routed fp16 GEMM (128x128, 2-stage, occ2) -----------------
template <bool RELU, bool HAS_EXTRA, bool OUT_HALF>
__global__ void __launch_bounds__(256, 2) k_std16(
    const __half* __restrict__ Ab, const __half* __restrict__ Wb,
    const float* __restrict__ biasb, const __half* __restrict__ extrab,
    void* __restrict__ Cb, int N, int K) {
    int e = blockIdx.z, off = g_offsets[e], M = g_offsets[e + 1] - off;
    int m0 = blockIdx.y * 128;
    if (m0 >= M) return;
    int n0 = blockIdx.x * 128;
    const __half* A = Ab + (size_t)off * K;
    const __half* Wt = Wb + ((size_t)e * N + n0) * K;
    const float* bias = biasb + (size_t)e * N + n0;

    extern __shared__ char sm_raw[];
    uint32_t sb = (smem_u32(sm_raw) + 1023u) & ~1023u;
    int tid = threadIdx.x, warp = tid >> 5, lane = tid & 31;
    int wm = (warp & 1) * 64, wn = (warp >> 1) * 32;

    int lrow[4], lch[4];
#pragma unroll
    for (int i = 0; i < 4; i++) { int idx = tid + i * 256; lrow[i] = idx >> 3; lch[i] = idx & 7; }

    float c[4][4][4];
#pragma unroll
    for (int a = 0; a < 4; a++)
#pragma unroll
        for (int b = 0; b < 4; b++)
#pragma unroll
            for (int q = 0; q < 4; q++) c[a][b][q] = 0.f;

    const int nk = K >> 6;
    auto issue = [&](int kt, int s) {
        uint32_t st = sb + (uint32_t)s * 32768;
#pragma unroll
        for (int i = 0; i < 4; i++) {
            int r = lrow[i];
            uint32_t so = swz((uint32_t)(r * 128 + lch[i] * 16));
            CPA(st + so, (const char*)(A + (size_t)(m0 + r) * K + kt * 64 + lch[i] * 8),
                (m0 + r < M) ? 16 : 0);
            CPA(st + 16384 + so, (const char*)(Wt + (size_t)r * K + kt * 64 + lch[i] * 8), 16);
        }
    };
    issue(0, 0); CPCOMMIT();
    for (int kt = 0; kt < nk; kt++) {
        int s = kt & 1;
        if (kt + 1 < nk) { issue(kt + 1, s ^ 1); CPCOMMIT(); CPWAIT(1); }
        else CPWAIT(0);
        __syncthreads();
        uint32_t ab = sb + (uint32_t)s * 32768, bbs = ab + 16384;
#pragma unroll
        for (int ks = 0; ks < 4; ks++) {
            uint32_t Af[4][4], Bf[4][2];
#pragma unroll
            for (int mi = 0; mi < 4; mi++) {
                uint32_t o = swz((uint32_t)((wm + mi * 16 + (lane & 15)) * 128 + ks * 32 + (lane >> 4) * 16));
                LDSM4(Af[mi][0], Af[mi][1], Af[mi][2], Af[mi][3], ab + o);
            }
#pragma unroll
            for (int p = 0; p < 2; p++) {
                uint32_t o = swz((uint32_t)((wn + p * 16 + (lane & 15)) * 128 + ks * 32 + (lane >> 4) * 16));
                uint32_t r0, r1, r2, r3;
                LDSM4(r0, r1, r2, r3, bbs + o);
                Bf[2 * p][0] = r0; Bf[2 * p][1] = r2; Bf[2 * p + 1][0] = r1; Bf[2 * p + 1][1] = r3;
            }
#pragma unroll
            for (int mi = 0; mi < 4; mi++)
#pragma unroll
                for (int ni = 0; ni < 4; ni++)
                    MMA16(c[mi][ni], Af[mi], Bf[ni][0], Bf[ni][1]);
        }
        __syncthreads();
    }
#pragma unroll
    for (int mi = 0; mi < 4; mi++)
#pragma unroll
        for (int ni = 0; ni < 4; ni++) {
            int col = wn + ni * 8 + (lane & 3) * 2;
            float b0 = bias[col], b1v = bias[col + 1];
#pragma unroll
            for (int h = 0; h < 2; h++) {
                int r = m0 + wm + mi * 16 + (lane >> 2) + h * 8;
                if (r < M) {
                    float v0 = c[mi][ni][2 * h] + b0, v1 = c[mi][ni][2 * h + 1] + b1v;
                    if (HAS_EXTRA) {
                        float2 ex = __half22float2(
                            *(const __half2*)(extrab + ((size_t)off + r) * N + n0 + col));
                        v0 += ex.x; v1 += ex.y;
                    }
                    if (RELU) { v0 = fmaxf(v0, 0.f); v1 = fmaxf(v1, 0.f); }
                    if (OUT_HALF)
                        *(__half2*)((__half*)Cb + ((size_t)off + r) * N + n0 + col) =
                            __halves2half2(__float2half_rn(v0), __float2half_rn(v1));
                    else
                        *(float2*)((float*)Cb + ((size_t)off + r) * N + n0 + col) =
                            make_float2(v0, v1);
                }
            }
        }
}

// ------------------------- routing / small kernels --------------------------
__global__ void k_zero() { if (threadIdx.x < NE) g_counts[threadIdx.x] = 0; }

__global__ void k_gating2(const float* __restrict__ gw2, const float* __restrict__ gb2) {
    int warp_g = (blockIdx.x * blockDim.x + threadIdx.x) >> 5;
    if (warp_g >= NB) return;
    int lane = threadIdx.x & 31;
    const float* hrow = g_h1 + (size_t)warp_g * GHID;
    float acc[NE];
#pragma unroll
    for (int e = 0; e < NE; e++) acc[e] = 0.f;
    for (int g = lane; g < GHID; g += 32) {
        float hv = hrow[g];
        const float* wr = gw2 + (size_t)g * NE;
#pragma unroll
        for (int e = 0; e < NE; e++) acc[e] = fmaf(hv, wr[e], acc[e]);
    }
#pragma unroll
    for (int e = 0; e < NE; e++)
#pragma unroll
        for (int s = 16; s > 0; s >>= 1) acc[e] += __shfl_xor_sync(0xffffffffu, acc[e], s);
    if (lane == 0) {
#pragma unroll
        for (int e = 0; e < NE; e++) acc[e] += gb2[e];
        int i1 = 0;
#pragma unroll
        for (int e = 1; e < NE; e++) if (acc[e] > acc[i1]) i1 = e;
        int i2 = (i1 == 0) ? 1 : 0;
#pragma unroll
        for (int e = 0; e < NE; e++) if (e != i1 && acc[e] > acc[i2]) i2 = e;
        float e2 = expf(acc[i2] - acc[i1]);
        float inv = 1.f / (1.f + e2);
        g_topk_e[2 * warp_g] = i1;   g_topk_e[2 * warp_g + 1] = i2;
        g_topk_w[2 * warp_g] = inv;  g_topk_w[2 * warp_g + 1] = e2 * inv;
        atomicAdd(&g_counts[i1], 1); atomicAdd(&g_counts[i2], 1);
    }
}

__global__ void k_offsets() {
    if (threadIdx.x == 0) {
        int acc = 0;
#pragma unroll
        for (int e = 0; e < NE; e++) { g_offsets[e] = acc; g_cursor[e] = acc; acc += g_counts[e]; }
        g_offsets[NE] = acc;
    }
}

__global__ void k_fill() {
    int t = blockIdx.x * blockDim.x + threadIdx.x;
    if (t >= NB) return;
#pragma unroll
    for (int k = 0; k < 2; k++) {
        int e = g_topk_e[2 * t + k];
        int pos = atomicAdd(&g_cursor[e], 1);
        g_slot_token[pos] = t;
        g_token_slot[2 * t + k] = pos;
    }
}

__global__ void k_gather(const float* __restrict__ x) {
    int s = blockIdx.x;
    int tok = g_slot_token[s];
    float4 v = ((const float4*)(x + (size_t)tok * DIN))[threadIdx.x];
    __half2* dst = (__half2*)(g_Xg + (size_t)s * DIN);
    dst[2 * threadIdx.x]     = __halves2half2(__float2half_rn(v.x), __float2half_rn(v.y));
    dst[2 * threadIdx.x + 1] = __halves2half2(__float2half_rn(v.z), __float2half_rn(v.w));
}

__global__ void k_combine(float* __restrict__ out) {
    int t = blockIdx.x, i = threadIdx.x;
    int s0 = g_token_slot[2 * t], s1 = g_token_slot[2 * t + 1];
    float w0 = g_topk_w[2 * t], w1 = g_topk_w[2 * t + 1];
    float4 y0 = ((const float4*)(g_Y + (size_t)s0 * DOUT))[i];
    float4 y1 = ((const float4*)(g_Y + (size_t)s1 * DOUT))[i];
    float4 o;
    o.x = w0 * y0.x + w1 * y1.x;  o.y = w0 * y0.y + w1 * y1.y;
    o.z = w0 * y0.z + w1 * y1.z;  o.w = w0 * y0.w + w1 * y1.w;
    ((float4*)out)[(size_t)t * (DOUT / 4) + i] = o;
}

// ------------------------------- launch -------------------------------------
extern "C" void kernel_launch(void* const* d_in, const int* in_sizes, int n_in,
                              void* d_out, int out_size) {
    const float* x   = (const float*)d_in[0];
    const float* w1  = (const float*)d_in[1];
    const float* b1  = (const float*)d_in[2];
    const float* w2  = (const float*)d_in[3];
    const float* b2  = (const float*)d_in[4];
    const float* w3  = (const float*)d_in[5];
    const float* b3  = (const float*)d_in[6];
    const float* wp  = (const float*)d_in[7];
    const float* bp  = (const float*)d_in[8];
    const float* gw1 = (const float*)d_in[9];
    const float* gb1 = (const float*)d_in[10];
    const float* gw2 = (const float*)d_in[11];
    const float* gb2 = (const float*)d_in[12];
    float* out = (float*)d_out;

    __half *w1t, *wpt, *w2t, *w3t, *gwh, *gwl, *Xg, *H, *O, *P;
    float *Y;
    cudaGetSymbolAddress((void**)&w1t, g_w1t);
    cudaGetSymbolAddress((void**)&wpt, g_wpt);
    cudaGetSymbolAddress((void**)&w2t, g_w2t);
    cudaGetSymbolAddress((void**)&w3t, g_w3t);
    cudaGetSymbolAddress((void**)&gwh, g_gwh);
    cudaGetSymbolAddress((void**)&gwl, g_gwl);
    cudaGetSymbolAddress((void**)&Xg,  g_Xg);
    cudaGetSymbolAddress((void**)&H,   g_H);
    cudaGetSymbolAddress((void**)&O,   g_O);
    cudaGetSymbolAddress((void**)&P,   g_P);
    cudaGetSymbolAddress((void**)&Y,   g_Y);

    auto* T1 = k_std16<true,  false, true>;    // H = relu(Xg@w1 + b1)
    auto* Tp = k_std16<false, false, true>;    // P = Xg@wp + bp
    auto* T2 = k_std16<true,  true,  true>;    // O = relu(H@w2 + P + b2)
    auto* T3 = k_std16<false, false, false>;   // Y = O@w3 + b3
    const int SM_STD  = 2 * 32768;
    const int SM_GATE = 2 * 49152;
    cudaFuncSetAttribute(T1, cudaFuncAttributeMaxDynamicSharedMemorySize, SM_STD);
    cudaFuncSetAttribute(Tp, cudaFuncAttributeMaxDynamicSharedMemorySize, SM_STD);
    cudaFuncSetAttribute(T2, cudaFuncAttributeMaxDynamicSharedMemorySize, SM_STD);
    cudaFuncSetAttribute(T3, cudaFuncAttributeMaxDynamicSharedMemorySize, SM_STD);
    cudaFuncSetAttribute(k_gate16, cudaFuncAttributeMaxDynamicSharedMemorySize, SM_GATE);

    static cudaStream_t s_aux = nullptr;
    static cudaEvent_t evFork = nullptr, evW1 = nullptr, evW2 = nullptr;
    if (s_aux == nullptr) {
        cudaStreamCreateWithFlags(&s_aux, cudaStreamNonBlocking);
        cudaEventCreateWithFlags(&evFork, cudaEventDisableTiming);
        cudaEventCreateWithFlags(&evW1, cudaEventDisableTiming);
        cudaEventCreateWithFlags(&evW2, cudaEventDisableTiming);
    }

    // Fork: layer-1 weight transposes first (needed earliest), then layer-2/3
    // transposes which overlap the T1/Tp GEMMs on the main stream.
    cudaEventRecord(evFork, 0);
    cudaStreamWaitEvent(s_aux, evFork, 0);
    k_t16<false><<<dim3(HID / 32, DIN / 64, NE), 256, 0, s_aux>>>(w1, w1t, nullptr, DIN, HID);
    k_t16<false><<<dim3(HID / 32, DIN / 64, NE), 256, 0, s_aux>>>(wp, wpt, nullptr, DIN, HID);
    cudaEventRecord(evW1, s_aux);
    k_t16<false><<<dim3(HID / 32, HID / 64, NE), 256, 0, s_aux>>>(w2, w2t, nullptr, HID, HID);
    k_t16<false><<<dim3(DOUT / 32, HID / 64, NE), 256, 0, s_aux>>>(w3, w3t, nullptr, HID, DOUT);
    cudaEventRecord(evW2, s_aux);

    // Gating chain on the main stream.
    k_zero<<<1, 32>>>();
    k_split_x<<<(NB * DIN / 4) / 256, 256>>>(x);
    k_t16<true><<<dim3(GHID / 32, DIN / 64, 1), 256>>>(gw1, gwh, gwl, DIN, GHID);
    k_gate16<<<dim3(GHID / 64, NB / 128), 256, SM_GATE>>>(gb1);
    k_gating2<<<NB / 8, 256>>>(gw2, gb2);
    k_offsets<<<1, 32>>>();
    k_fill<<<NB / 256, 256>>>();
    k_gather<<<NSLOT, 256>>>(x);

    // Join 1: T1/Tp need only w1t/wpt. w2t/w3t still transpose underneath.
    cudaStreamWaitEvent(0, evW1, 0);
    T1<<<dim3(HID / 128, NB / 128, NE), 256, SM_STD>>>(Xg, w1t, b1, nullptr, H, HID, DIN);
    Tp<<<dim3(HID / 128, NB / 128, NE), 256, SM_STD>>>(Xg, wpt, bp, nullptr, P, HID, DIN);
    // Join 2: T2/T3 need w2t/w3t.
    cudaStreamWaitEvent(0, evW2, 0);
    T2<<<dim3(HID / 128, NB / 128, NE), 256, SM_STD>>>(H, w2t, b2, P, O, HID, HID);
    T3<<<dim3(DOUT / 128, NB / 128, NE), 256, SM_STD>>>(O, w3t, b3, nullptr, Y, DOUT, HID);
    k_combine<<<NB, 256>>>(out);
}

// round 15
// speedup vs baseline: 1.0088x; 1.0088x over previous
#include <cuda_runtime.h>
#include <cuda_fp16.h>
#include <cstdint>
#include <cstddef>
#include <math.h>

#define NB    8192
#define DIN   1024
#define HID   2048
#define DOUT  1024
#define NE    8
#define GHID  1024
#define NSLOT (NB * 2)
#define MAXT  144   // max row-tiles across experts (<=135 actual)

// ------------------------- device scratch (static) -------------------------
__device__ float  g_h1[(size_t)NB * GHID];
__device__ __half g_xh[(size_t)NB * DIN];
__device__ __half g_xl[(size_t)NB * DIN];
__device__ __half g_gwh[(size_t)GHID * DIN];
__device__ __half g_gwl[(size_t)GHID * DIN];
__device__ __half g_Xg[(size_t)NSLOT * DIN];
__device__ __half g_H [(size_t)NSLOT * HID];
__device__ __half g_P [(size_t)NSLOT * HID];
__device__ __half g_O [(size_t)NSLOT * HID];
__device__ float  g_Y [(size_t)NSLOT * DOUT];
__device__ __half g_w1t[(size_t)NE * DIN * HID];
__device__ __half g_wpt[(size_t)NE * DIN * HID];
__device__ __half g_w2t[(size_t)NE * HID * HID];
__device__ __half g_w3t[(size_t)NE * HID * DOUT];
__device__ int   g_topk_e[NSLOT];
__device__ float g_topk_w[NSLOT];
__device__ int   g_token_slot[NSLOT];
__device__ int   g_slot_token[NSLOT];
__device__ int   g_counts[NE];
__device__ int   g_offsets[NE + 1];
__device__ int   g_cursor[NE];
__device__ int   g_ntiles;
__device__ int   g_tile_e[MAXT];
__device__ int   g_tile_m0[MAXT];

// ------------------------------ helpers ------------------------------------
__device__ __forceinline__ uint32_t smem_u32(const void* p) {
    uint32_t a;
    asm("{ .reg .u64 t; cvta.to.shared.u64 t, %1; cvt.u32.u64 %0, t; }" : "=r"(a) : "l"(p));
    return a;
}
__device__ __forceinline__ uint32_t swz(uint32_t o) { return o ^ ((o >> 3) & 0x70); }

#define LDSM4(r0, r1, r2, r3, addr) \
    asm volatile("ldmatrix.sync.aligned.m8n8.x4.shared.b16 {%0,%1,%2,%3}, [%4];" \
                 : "=r"(r0), "=r"(r1), "=r"(r2), "=r"(r3) : "r"(addr))

#define MMA16(c, a, b0, b1) \
    asm volatile("mma.sync.aligned.m16n8k16.row.col.f32.f16.f16.f32 " \
                 "{%0,%1,%2,%3}, {%4,%5,%6,%7}, {%8,%9}, {%0,%1,%2,%3};" \
                 : "+f"((c)[0]), "+f"((c)[1]), "+f"((c)[2]), "+f"((c)[3]) \
                 : "r"((a)[0]), "r"((a)[1]), "r"((a)[2]), "r"((a)[3]), "r"(b0), "r"(b1))

#define CPA(dst, src, zf) \
    asm volatile("cp.async.cg.shared.global [%0], [%1], 16, %2;" :: "r"(dst), "l"(src), "r"(zf))
#define CPCOMMIT() asm volatile("cp.async.commit_group;")
#define CPWAIT(n)  asm volatile("cp.async.wait_group %0;" :: "n"(n))

// -------- weight transpose float[K][N] -> half[N][K], 64K x 32N tiles -------
template <bool SPLIT>
__global__ void __launch_bounds__(256) k_t16(
    const float* __restrict__ in, __half* __restrict__ oh, __half* __restrict__ ol,
    int K, int N) {
    __shared__ float t[64][33];
    size_t eo = (size_t)blockIdx.z * K * N;
    int k0 = blockIdx.y * 64, n0 = blockIdx.x * 32;
#pragma unroll
    for (int i = 0; i < 8; i++) {
        int idx = threadIdx.x + i * 256;
        int k = idx >> 5, n = idx & 31;
        t[k][n] = in[eo + (size_t)(k0 + k) * N + n0 + n];
    }
    __syncthreads();
#pragma unroll
    for (int i = 0; i < 4; i++) {
        int idx = threadIdx.x + i * 256;
        int n = idx >> 5, kk = idx & 31;
        float v0 = t[2 * kk][n], v1 = t[2 * kk + 1][n];
        __half h0 = __float2half_rn(v0), h1 = __float2half_rn(v1);
        size_t oi = eo + (size_t)(n0 + n) * K + k0 + 2 * kk;
        *(__half2*)(oh + oi) = __halves2half2(h0, h1);
        if (SPLIT)
            *(__half2*)(ol + oi) = __halves2half2(
                __float2half_rn(v0 - __half2float(h0)),
                __float2half_rn(v1 - __half2float(h1)));
    }
}

// ------------------ x hi/lo split (+ counts zero in block 0) ----------------
__global__ void __launch_bounds__(256) k_split_x(const float* __restrict__ x) {
    if (blockIdx.x == 0 && threadIdx.x < NE) g_counts[threadIdx.x] = 0;
    size_t i = (size_t)blockIdx.x * 256 + threadIdx.x;
    float4 v = ((const float4*)x)[i];
    __half hx = __float2half_rn(v.x), hy = __float2half_rn(v.y);
    __half hz = __float2half_rn(v.z), hw = __float2half_rn(v.w);
    ((__half2*)g_xh)[2 * i]     = __halves2half2(hx, hy);
    ((__half2*)g_xh)[2 * i + 1] = __halves2half2(hz, hw);
    ((__half2*)g_xl)[2 * i] = __halves2half2(
        __float2half_rn(v.x - __half2float(hx)), __float2half_rn(v.y - __half2float(hy)));
    ((__half2*)g_xl)[2 * i + 1] = __halves2half2(
        __float2half_rn(v.z - __half2float(hz)), __float2half_rn(v.w - __half2float(hw)));
}

// ------- gating GEMM: fp16 split, 3 products, 2-stage, BN=64, occ-2 --------
__global__ void __launch_bounds__(256, 2) k_gate16(const float* __restrict__ gb1) {
    const int K = DIN;
    int m0 = blockIdx.y * 128, n0 = blockIdx.x * 64;
    extern __shared__ char sm_raw[];
    uint32_t sb = (smem_u32(sm_raw) + 1023u) & ~1023u;
    int tid = threadIdx.x, warp = tid >> 5, lane = tid & 31;
    int wm = (warp & 1) * 64, wn = (warp >> 1) * 16;

    int lrow[4], lch[4], brow[2], bch[2];
#pragma unroll
    for (int i = 0; i < 4; i++) { int idx = tid + i * 256; lrow[i] = idx >> 3; lch[i] = idx & 7; }
#pragma unroll
    for (int i = 0; i < 2; i++) { int idx = tid + i * 256; brow[i] = idx >> 3; bch[i] = idx & 7; }

    float c[4][2][4];
#pragma unroll
    for (int a = 0; a < 4; a++)
#pragma unroll
        for (int b = 0; b < 2; b++)
#pragma unroll
            for (int q = 0; q < 4; q++) c[a][b][q] = 0.f;

    const int nk = K >> 6;
    auto issue = [&](int kt, int s) {
        uint32_t st = sb + (uint32_t)s * 49152;
#pragma unroll
        for (int i = 0; i < 4; i++) {
            int r = lrow[i];
            uint32_t so = swz((uint32_t)(r * 128 + lch[i] * 16));
            size_t go = (size_t)(m0 + r) * K + kt * 64 + lch[i] * 8;
            CPA(st + so,         (const char*)(g_xh + go), 16);
            CPA(st + 16384 + so, (const char*)(g_xl + go), 16);
        }
#pragma unroll
        for (int i = 0; i < 2; i++) {
            int r = brow[i];
            uint32_t so = swz((uint32_t)(r * 128 + bch[i] * 16));
            size_t gw = (size_t)(n0 + r) * K + kt * 64 + bch[i] * 8;
            CPA(st + 32768 + so, (const char*)(g_gwh + gw), 16);
            CPA(st + 40960 + so, (const char*)(g_gwl + gw), 16);
        }
    };
    issue(0, 0); CPCOMMIT();
    for (int kt = 0; kt < nk; kt++) {
        int s = kt & 1;
        if (kt + 1 < nk) { issue(kt + 1, s ^ 1); CPCOMMIT(); CPWAIT(1); }
        else CPWAIT(0);
        __syncthreads();
        uint32_t ah = sb + (uint32_t)s * 49152, al = ah + 16384, bh = ah + 32768, bl = ah + 40960;
#pragma unroll
        for (int ks = 0; ks < 4; ks++) {
            uint32_t A[4][4], L[4][4], BH[2][2], BL[2][2];
#pragma unroll
            for (int mi = 0; mi < 4; mi++) {
                uint32_t o = swz((uint32_t)((wm + mi * 16 + (lane & 15)) * 128 + ks * 32 + (lane >> 4) * 16));
                LDSM4(A[mi][0], A[mi][1], A[mi][2], A[mi][3], ah + o);
                LDSM4(L[mi][0], L[mi][1], L[mi][2], L[mi][3], al + o);
            }
            {
                uint32_t o = swz((uint32_t)((wn + (lane & 15)) * 128 + ks * 32 + (lane >> 4) * 16));
                uint32_t r0, r1, r2, r3;
                LDSM4(r0, r1, r2, r3, bh + o);
                BH[0][0] = r0; BH[0][1] = r2; BH[1][0] = r1; BH[1][1] = r3;
                LDSM4(r0, r1, r2, r3, bl + o);
                BL[0][0] = r0; BL[0][1] = r2; BL[1][0] = r1; BL[1][1] = r3;
            }
#pragma unroll
            for (int mi = 0; mi < 4; mi++)
#pragma unroll
                for (int ni = 0; ni < 2; ni++) {
                    MMA16(c[mi][ni], A[mi], BH[ni][0], BH[ni][1]);
                    MMA16(c[mi][ni], L[mi], BH[ni][0], BH[ni][1]);
                    MMA16(c[mi][ni], A[mi], BL[ni][0], BL[ni][1]);
                }
        }
        __syncthreads();
    }
#pragma unroll
    for (int mi = 0; mi < 4; mi++)
#pragma unroll
        for (int ni = 0; ni < 2; ni++) {
            int col = n0 + wn + ni * 8 + (lane & 3) * 2;
            float b0 = gb1[col], b1v = gb1[col + 1];
#pragma unroll
            for (int h = 0; h < 2; h++) {
                int r = m0 + wm + mi * 16 + (lane >> 2) + h * 8;
                *(float2*)(g_h1 + (size_t)r * GHID + col) =
                    make_float2(fmaxf(c[mi][ni][2 * h] + b0, 0.f),
                                fmaxf(c[mi][ni][2 * h + 1] + b1v, 0.f));
            }
        }
}

// ------- routed fp16 GEMM (128x128, 2-stage, occ2), tile-list grid ---------
template <bool RELU, bool HAS_EXTRA, bool OUT_HALF>
__global__ void __launch_bounds__(256, 2) k_std16(
    const __half* __restrict__ Ab, const __half* __restrict__ Wb,
    const float* __restrict__ biasb, const __half* __restrict__ extrab,
    void* __restrict__ Cb, int N, int K) {
    int t = blockIdx.y;
    if (t >= g_ntiles) return;
    int e = g_tile_e[t];
    int m0 = g_tile_m0[t];
    int off = g_offsets[e], M = g_offsets[e + 1] - off;
    int n0 = blockIdx.x * 128;
    const __half* A = Ab + (size_t)off * K;
    const __half* Wt = Wb + ((size_t)e * N + n0) * K;
    const float* bias = biasb + (size_t)e * N + n0;

    extern __shared__ char sm_raw[];
    uint32_t sb = (smem_u32(sm_raw) + 1023u) & ~1023u;
    int tid = threadIdx.x, warp = tid >> 5, lane = tid & 31;
    int wm = (warp & 1) * 64, wn = (warp >> 1) * 32;

    int lrow[4], lch[4];
#pragma unroll
    for (int i = 0; i < 4; i++) { int idx = tid + i * 256; lrow[i] = idx >> 3; lch[i] = idx & 7; }

    float c[4][4][4];
#pragma unroll
    for (int a = 0; a < 4; a++)
#pragma unroll
        for (int b = 0; b < 4; b++)
#pragma unroll
            for (int q = 0; q < 4; q++) c[a][b][q] = 0.f;

    const int nk = K >> 6;
    auto issue = [&](int kt, int s) {
        uint32_t st = sb + (uint32_t)s * 32768;
#pragma unroll
        for (int i = 0; i < 4; i++) {
            int r = lrow[i];
            uint32_t so = swz((uint32_t)(r * 128 + lch[i] * 16));
            CPA(st + so, (const char*)(A + (size_t)(m0 + r) * K + kt * 64 + lch[i] * 8),
                (m0 + r < M) ? 16 : 0);
            CPA(st + 16384 + so, (const char*)(Wt + (size_t)r * K + kt * 64 + lch[i] * 8), 16);
        }
    };
    issue(0, 0); CPCOMMIT();
    for (int kt = 0; kt < nk; kt++) {
        int s = kt & 1;
        if (kt + 1 < nk) { issue(kt + 1, s ^ 1); CPCOMMIT(); CPWAIT(1); }
        else CPWAIT(0);
        __syncthreads();
        uint32_t ab = sb + (uint32_t)s * 32768, bbs = ab + 16384;
#pragma unroll
        for (int ks = 0; ks < 4; ks++) {
            uint32_t Af[4][4], Bf[4][2];
#pragma unroll
            for (int mi = 0; mi < 4; mi++) {
                uint32_t o = swz((uint32_t)((wm + mi * 16 + (lane & 15)) * 128 + ks * 32 + (lane >> 4) * 16));
                LDSM4(Af[mi][0], Af[mi][1], Af[mi][2], Af[mi][3], ab + o);
            }
#pragma unroll
            for (int p = 0; p < 2; p++) {
                uint32_t o = swz((uint32_t)((wn + p * 16 + (lane & 15)) * 128 + ks * 32 + (lane >> 4) * 16));
                uint32_t r0, r1, r2, r3;
                LDSM4(r0, r1, r2, r3, bbs + o);
                Bf[2 * p][0] = r0; Bf[2 * p][1] = r2; Bf[2 * p + 1][0] = r1; Bf[2 * p + 1][1] = r3;
            }
#pragma unroll
            for (int mi = 0; mi < 4; mi++)
#pragma unroll
                for (int ni = 0; ni < 4; ni++)
                    MMA16(c[mi][ni], Af[mi], Bf[ni][0], Bf[ni][1]);
        }
        __syncthreads();
    }
#pragma unroll
    for (int mi = 0; mi < 4; mi++)
#pragma unroll
        for (int ni = 0; ni < 4; ni++) {
            int col = wn + ni * 8 + (lane & 3) * 2;
            float b0 = bias[col], b1v = bias[col + 1];
#pragma unroll
            for (int h = 0; h < 2; h++) {
                int r = m0 + wm + mi * 16 + (lane >> 2) + h * 8;
                if (r < M) {
                    float v0 = c[mi][ni][2 * h] + b0, v1 = c[mi][ni][2 * h + 1] + b1v;
                    if (HAS_EXTRA) {
                        float2 ex = __half22float2(
                            *(const __half2*)(extrab + ((size_t)off + r) * N + n0 + col));
                        v0 += ex.x; v1 += ex.y;
                    }
                    if (RELU) { v0 = fmaxf(v0, 0.f); v1 = fmaxf(v1, 0.f); }
                    if (OUT_HALF)
                        *(__half2*)((__half*)Cb + ((size_t)off + r) * N + n0 + col) =
                            __halves2half2(__float2half_rn(v0), __float2half_rn(v1));
                    else
                        *(float2*)((float*)Cb + ((size_t)off + r) * N + n0 + col) =
                            make_float2(v0, v1);
                }
            }
        }
}

// ------------------------- routing / small kernels --------------------------
__global__ void k_gating2(const float* __restrict__ gw2, const float* __restrict__ gb2) {
    int warp_g = (blockIdx.x * blockDim.x + threadIdx.x) >> 5;
    if (warp_g >= NB) return;
    int lane = threadIdx.x & 31;
    const float* hrow = g_h1 + (size_t)warp_g * GHID;
    float acc[NE];
#pragma unroll
    for (int e = 0; e < NE; e++) acc[e] = 0.f;
    for (int g = lane; g < GHID; g += 32) {
        float hv = hrow[g];
        const float* wr = gw2 + (size_t)g * NE;
#pragma unroll
        for (int e = 0; e < NE; e++) acc[e] = fmaf(hv, wr[e], acc[e]);
    }
#pragma unroll
    for (int e = 0; e < NE; e++)
#pragma unroll
        for (int s = 16; s > 0; s >>= 1) acc[e] += __shfl_xor_sync(0xffffffffu, acc[e], s);
    if (lane == 0) {
#pragma unroll
        for (int e = 0; e < NE; e++) acc[e] += gb2[e];
        int i1 = 0;
#pragma unroll
        for (int e = 1; e < NE; e++) if (acc[e] > acc[i1]) i1 = e;
        int i2 = (i1 == 0) ? 1 : 0;
#pragma unroll
        for (int e = 0; e < NE; e++) if (e != i1 && acc[e] > acc[i2]) i2 = e;
        float e2 = expf(acc[i2] - acc[i1]);
        float inv = 1.f / (1.f + e2);
        g_topk_e[2 * warp_g] = i1;   g_topk_e[2 * warp_g + 1] = i2;
        g_topk_w[2 * warp_g] = inv;  g_topk_w[2 * warp_g + 1] = e2 * inv;
        atomicAdd(&g_counts[i1], 1); atomicAdd(&g_counts[i2], 1);
    }
}

__global__ void k_offsets() {
    if (threadIdx.x == 0) {
        int acc = 0;
#pragma unroll
        for (int e = 0; e < NE; e++) { g_offsets[e] = acc; g_cursor[e] = acc; acc += g_counts[e]; }
        g_offsets[NE] = acc;
        int nt = 0;
        for (int e = 0; e < NE; e++) {
            int cnt = g_counts[e];
            for (int m0 = 0; m0 < cnt; m0 += 128) {
                g_tile_e[nt] = e;
                g_tile_m0[nt] = m0;
                nt++;
            }
        }
        g_ntiles = nt;
    }
}

__global__ void k_fill() {
    int t = blockIdx.x * blockDim.x + threadIdx.x;
    if (t >= NB) return;
#pragma unroll
    for (int k = 0; k < 2; k++) {
        int e = g_topk_e[2 * t + k];
        int pos = atomicAdd(&g_cursor[e], 1);
        g_slot_token[pos] = t;
        g_token_slot[2 * t + k] = pos;
    }
}

__global__ void k_gather(const float* __restrict__ x) {
    int s = blockIdx.x;
    int tok = g_slot_token[s];
    float4 v = ((const float4*)(x + (size_t)tok * DIN))[threadIdx.x];
    __half2* dst = (__half2*)(g_Xg + (size_t)s * DIN);
    dst[2 * threadIdx.x]     = __halves2half2(__float2half_rn(v.x), __float2half_rn(v.y));
    dst[2 * threadIdx.x + 1] = __halves2half2(__float2half_rn(v.z), __float2half_rn(v.w));
}

__global__ void k_combine(float* __restrict__ out) {
    int t = blockIdx.x, i = threadIdx.x;
    int s0 = g_token_slot[2 * t], s1 = g_token_slot[2 * t + 1];
    float w0 = g_topk_w[2 * t], w1 = g_topk_w[2 * t + 1];
    float4 y0 = ((const float4*)(g_Y + (size_t)s0 * DOUT))[i];
    float4 y1 = ((const float4*)(g_Y + (size_t)s1 * DOUT))[i];
    float4 o;
    o.x = w0 * y0.x + w1 * y1.x;  o.y = w0 * y0.y + w1 * y1.y;
    o.z = w0 * y0.z + w1 * y1.z;  o.w = w0 * y0.w + w1 * y1.w;
    ((float4*)out)[(size_t)t * (DOUT / 4) + i] = o;
}

// ------------------------------- launch -------------------------------------
extern "C" void kernel_launch(void* const* d_in, const int* in_sizes, int n_in,
                              void* d_out, int out_size) {
    const float* x   = (const float*)d_in[0];
    const float* w1  = (const float*)d_in[1];
    const float* b1  = (const float*)d_in[2];
    const float* w2  = (const float*)d_in[3];
    const float* b2  = (const float*)d_in[4];
    const float* w3  = (const float*)d_in[5];
    const float* b3  = (const float*)d_in[6];
    const float* wp  = (const float*)d_in[7];
    const float* bp  = (const float*)d_in[8];
    const float* gw1 = (const float*)d_in[9];
    const float* gb1 = (const float*)d_in[10];
    const float* gw2 = (const float*)d_in[11];
    const float* gb2 = (const float*)d_in[12];
    float* out = (float*)d_out;

    __half *w1t, *wpt, *w2t, *w3t, *gwh, *gwl, *Xg, *H, *O, *P;
    float *Y;
    cudaGetSymbolAddress((void**)&w1t, g_w1t);
    cudaGetSymbolAddress((void**)&wpt, g_wpt);
    cudaGetSymbolAddress((void**)&w2t, g_w2t);
    cudaGetSymbolAddress((void**)&w3t, g_w3t);
    cudaGetSymbolAddress((void**)&gwh, g_gwh);
    cudaGetSymbolAddress((void**)&gwl, g_gwl);
    cudaGetSymbolAddress((void**)&Xg,  g_Xg);
    cudaGetSymbolAddress((void**)&H,   g_H);
    cudaGetSymbolAddress((void**)&O,   g_O);
    cudaGetSymbolAddress((void**)&P,   g_P);
    cudaGetSymbolAddress((void**)&Y,   g_Y);

    auto* T1 = k_std16<true,  false, true>;    // H = relu(Xg@w1 + b1)
    auto* Tp = k_std16<false, false, true>;    // P = Xg@wp + bp
    auto* T2 = k_std16<true,  true,  true>;    // O = relu(H@w2 + P + b2)
    auto* T3 = k_std16<false, false, false>;   // Y = O@w3 + b3
    const int SM_STD  = 2 * 32768;
    const int SM_GATE = 2 * 49152;
    cudaFuncSetAttribute(T1, cudaFuncAttributeMaxDynamicSharedMemorySize, SM_STD);
    cudaFuncSetAttribute(Tp, cudaFuncAttributeMaxDynamicSharedMemorySize, SM_STD);
    cudaFuncSetAttribute(T2, cudaFuncAttributeMaxDynamicSharedMemorySize, SM_STD);
    cudaFuncSetAttribute(T3, cudaFuncAttributeMaxDynamicSharedMemorySize, SM_STD);
    cudaFuncSetAttribute(k_gate16, cudaFuncAttributeMaxDynamicSharedMemorySize, SM_GATE);

    static cudaStream_t s_aux = nullptr;
    static cudaEvent_t evFork = nullptr, evW1 = nullptr, evW2 = nullptr;
    if (s_aux == nullptr) {
        cudaStreamCreateWithFlags(&s_aux, cudaStreamNonBlocking);
        cudaEventCreateWithFlags(&evFork, cudaEventDisableTiming);
        cudaEventCreateWithFlags(&evW1, cudaEventDisableTiming);
        cudaEventCreateWithFlags(&evW2, cudaEventDisableTiming);
    }

    // Fork: weight transposes overlap the gating chain (fully hidden).
    cudaEventRecord(evFork, 0);
    cudaStreamWaitEvent(s_aux, evFork, 0);
    k_t16<false><<<dim3(HID / 32, DIN / 64, NE), 256, 0, s_aux>>>(w1, w1t, nullptr, DIN, HID);
    k_t16<false><<<dim3(HID / 32, DIN / 64, NE), 256, 0, s_aux>>>(wp, wpt, nullptr, DIN, HID);
    cudaEventRecord(evW1, s_aux);
    k_t16<false><<<dim3(HID / 32, HID / 64, NE), 256, 0, s_aux>>>(w2, w2t, nullptr, HID, HID);
    k_t16<false><<<dim3(DOUT / 32, HID / 64, NE), 256, 0, s_aux>>>(w3, w3t, nullptr, HID, DOUT);
    cudaEventRecord(evW2, s_aux);

    // Gating chain on the main stream.
    k_split_x<<<(NB * DIN / 4) / 256, 256>>>(x);
    k_t16<true><<<dim3(GHID / 32, DIN / 64, 1), 256>>>(gw1, gwh, gwl, DIN, GHID);
    k_gate16<<<dim3(GHID / 64, NB / 128), 256, SM_GATE>>>(gb1);
    k_gating2<<<NB / 8, 256>>>(gw2, gb2);
    k_offsets<<<1, 32>>>();
    k_fill<<<NB / 256, 256>>>();
    k_gather<<<NSLOT, 256>>>(x);

    // Expert GEMMs on compact tile-list grids.
    cudaStreamWaitEvent(0, evW1, 0);
    T1<<<dim3(HID / 128, MAXT), 256, SM_STD>>>(Xg, w1t, b1, nullptr, H, HID, DIN);
    Tp<<<dim3(HID / 128, MAXT), 256, SM_STD>>>(Xg, wpt, bp, nullptr, P, HID, DIN);
    cudaStreamWaitEvent(0, evW2, 0);
    T2<<<dim3(HID / 128, MAXT), 256, SM_STD>>>(H, w2t, b2, P, O, HID, HID);
    T3<<<dim3(DOUT / 128, MAXT), 256, SM_STD>>>(O, w3t, b3, nullptr, Y, DOUT, HID);
    k_combine<<<NB, 256>>>(out);
}

// round 16
// speedup vs baseline: 1.0105x; 1.0017x over previous
#include <cuda_runtime.h>
#include <cuda_fp16.h>
#include <cstdint>
#include <cstddef>
#include <math.h>

#define NB    8192
#define DIN   1024
#define HID   2048
#define DOUT  1024
#define NE    8
#define GHID  1024
#define NSLOT (NB * 2)
#define MAXT  144

// ------------------------- device scratch (static) -------------------------
__device__ float  g_h1[(size_t)NB * GHID];
__device__ __half g_xh[(size_t)NB * DIN];
__device__ __half g_xl[(size_t)NB * DIN];
__device__ __half g_gwh[(size_t)GHID * DIN];
__device__ __half g_gwl[(size_t)GHID * DIN];
__device__ __half g_Xg[(size_t)NSLOT * DIN];
__device__ __half g_H [(size_t)NSLOT * HID];
__device__ __half g_P [(size_t)NSLOT * HID];
__device__ __half g_O [(size_t)NSLOT * HID];
__device__ float  g_Y [(size_t)NSLOT * DOUT];
__device__ __half g_w1t[(size_t)NE * DIN * HID];
__device__ __half g_wpt[(size_t)NE * DIN * HID];
__device__ __half g_w2t[(size_t)NE * HID * HID];
__device__ __half g_w3t[(size_t)NE * HID * DOUT];
__device__ int   g_topk_e[NSLOT];
__device__ float g_topk_w[NSLOT];
__device__ int   g_token_slot[NSLOT];
__device__ int   g_slot_token[NSLOT];
__device__ int   g_counts[NE];
__device__ int   g_offsets[NE + 1];
__device__ int   g_cursor[NE];
__device__ int   g_ntiles;
__device__ int   g_tile_e[MAXT];
__device__ int   g_tile_m0[MAXT];

// ------------------------------ helpers ------------------------------------
__device__ __forceinline__ uint32_t smem_u32(const void* p) {
    uint32_t a;
    asm("{ .reg .u64 t; cvta.to.shared.u64 t, %1; cvt.u32.u64 %0, t; }" : "=r"(a) : "l"(p));
    return a;
}
__device__ __forceinline__ uint32_t swz(uint32_t o) { return o ^ ((o >> 3) & 0x70); }

#define LDSM4(r0, r1, r2, r3, addr) \
    asm volatile("ldmatrix.sync.aligned.m8n8.x4.shared.b16 {%0,%1,%2,%3}, [%4];" \
                 : "=r"(r0), "=r"(r1), "=r"(r2), "=r"(r3) : "r"(addr))

#define MMA16(c, a, b0, b1) \
    asm volatile("mma.sync.aligned.m16n8k16.row.col.f32.f16.f16.f32 " \
                 "{%0,%1,%2,%3}, {%4,%5,%6,%7}, {%8,%9}, {%0,%1,%2,%3};" \
                 : "+f"((c)[0]), "+f"((c)[1]), "+f"((c)[2]), "+f"((c)[3]) \
                 : "r"((a)[0]), "r"((a)[1]), "r"((a)[2]), "r"((a)[3]), "r"(b0), "r"(b1))

#define CPA(dst, src, zf) \
    asm volatile("cp.async.cg.shared.global [%0], [%1], 16, %2;" :: "r"(dst), "l"(src), "r"(zf))
#define CPCOMMIT() asm volatile("cp.async.commit_group;")
#define CPWAIT(n)  asm volatile("cp.async.wait_group %0;" :: "n"(n))

// -------- weight transpose float[K][N] -> half[N][K], 64K x 32N tiles -------
template <bool SPLIT>
__global__ void __launch_bounds__(256) k_t16(
    const float* __restrict__ in, __half* __restrict__ oh, __half* __restrict__ ol,
    int K, int N) {
    __shared__ float t[64][33];
    size_t eo = (size_t)blockIdx.z * K * N;
    int k0 = blockIdx.y * 64, n0 = blockIdx.x * 32;
#pragma unroll
    for (int i = 0; i < 8; i++) {
        int idx = threadIdx.x + i * 256;
        int k = idx >> 5, n = idx & 31;
        t[k][n] = in[eo + (size_t)(k0 + k) * N + n0 + n];
    }
    __syncthreads();
#pragma unroll
    for (int i = 0; i < 4; i++) {
        int idx = threadIdx.x + i * 256;
        int n = idx >> 5, kk = idx & 31;
        float v0 = t[2 * kk][n], v1 = t[2 * kk + 1][n];
        __half h0 = __float2half_rn(v0), h1 = __float2half_rn(v1);
        size_t oi = eo + (size_t)(n0 + n) * K + k0 + 2 * kk;
        *(__half2*)(oh + oi) = __halves2half2(h0, h1);
        if (SPLIT)
            *(__half2*)(ol + oi) = __halves2half2(
                __float2half_rn(v0 - __half2float(h0)),
                __float2half_rn(v1 - __half2float(h1)));
    }
}

// ------------------ x hi/lo split (+ counts zero in block 0) ----------------
__global__ void __launch_bounds__(256) k_split_x(const float* __restrict__ x) {
    if (blockIdx.x == 0 && threadIdx.x < NE) g_counts[threadIdx.x] = 0;
    size_t i = (size_t)blockIdx.x * 256 + threadIdx.x;
    float4 v = ((const float4*)x)[i];
    __half hx = __float2half_rn(v.x), hy = __float2half_rn(v.y);
    __half hz = __float2half_rn(v.z), hw = __float2half_rn(v.w);
    ((__half2*)g_xh)[2 * i]     = __halves2half2(hx, hy);
    ((__half2*)g_xh)[2 * i + 1] = __halves2half2(hz, hw);
    ((__half2*)g_xl)[2 * i] = __halves2half2(
        __float2half_rn(v.x - __half2float(hx)), __float2half_rn(v.y - __half2float(hy)));
    ((__half2*)g_xl)[2 * i + 1] = __halves2half2(
        __float2half_rn(v.z - __half2float(hz)), __float2half_rn(v.w - __half2float(hw)));
}

// ------- gating GEMM: fp16 split, 3 products, 2-stage, BN=64, occ-2 --------
__global__ void __launch_bounds__(256, 2) k_gate16(const float* __restrict__ gb1) {
    const int K = DIN;
    int m0 = blockIdx.y * 128, n0 = blockIdx.x * 64;
    extern __shared__ char sm_raw[];
    uint32_t sb = (smem_u32(sm_raw) + 1023u) & ~1023u;
    int tid = threadIdx.x, warp = tid >> 5, lane = tid & 31;
    int wm = (warp & 1) * 64, wn = (warp >> 1) * 16;

    int lrow[4], lch[4], brow[2], bch[2];
#pragma unroll
    for (int i = 0; i < 4; i++) { int idx = tid + i * 256; lrow[i] = idx >> 3; lch[i] = idx & 7; }
#pragma unroll
    for (int i = 0; i < 2; i++) { int idx = tid + i * 256; brow[i] = idx >> 3; bch[i] = idx & 7; }

    float c[4][2][4];
#pragma unroll
    for (int a = 0; a < 4; a++)
#pragma unroll
        for (int b = 0; b < 2; b++)
#pragma unroll
            for (int q = 0; q < 4; q++) c[a][b][q] = 0.f;

    const int nk = K >> 6;
    auto issue = [&](int kt, int s) {
        uint32_t st = sb + (uint32_t)s * 49152;
#pragma unroll
        for (int i = 0; i < 4; i++) {
            int r = lrow[i];
            uint32_t so = swz((uint32_t)(r * 128 + lch[i] * 16));
            size_t go = (size_t)(m0 + r) * K + kt * 64 + lch[i] * 8;
            CPA(st + so,         (const char*)(g_xh + go), 16);
            CPA(st + 16384 + so, (const char*)(g_xl + go), 16);
        }
#pragma unroll
        for (int i = 0; i < 2; i++) {
            int r = brow[i];
            uint32_t so = swz((uint32_t)(r * 128 + bch[i] * 16));
            size_t gw = (size_t)(n0 + r) * K + kt * 64 + bch[i] * 8;
            CPA(st + 32768 + so, (const char*)(g_gwh + gw), 16);
            CPA(st + 40960 + so, (const char*)(g_gwl + gw), 16);
        }
    };
    issue(0, 0); CPCOMMIT();
    for (int kt = 0; kt < nk; kt++) {
        int s = kt & 1;
        if (kt + 1 < nk) { issue(kt + 1, s ^ 1); CPCOMMIT(); CPWAIT(1); }
        else CPWAIT(0);
        __syncthreads();
        uint32_t ah = sb + (uint32_t)s * 49152, al = ah + 16384, bh = ah + 32768, bl = ah + 40960;
#pragma unroll
        for (int ks = 0; ks < 4; ks++) {
            uint32_t A[4][4], L[4][4], BH[2][2], BL[2][2];
#pragma unroll
            for (int mi = 0; mi < 4; mi++) {
                uint32_t o = swz((uint32_t)((wm + mi * 16 + (lane & 15)) * 128 + ks * 32 + (lane >> 4) * 16));
                LDSM4(A[mi][0], A[mi][1], A[mi][2], A[mi][3], ah + o);
                LDSM4(L[mi][0], L[mi][1], L[mi][2], L[mi][3], al + o);
            }
            {
                uint32_t o = swz((uint32_t)((wn + (lane & 15)) * 128 + ks * 32 + (lane >> 4) * 16));
                uint32_t r0, r1, r2, r3;
                LDSM4(r0, r1, r2, r3, bh + o);
                BH[0][0] = r0; BH[0][1] = r2; BH[1][0] = r1; BH[1][1] = r3;
                LDSM4(r0, r1, r2, r3, bl + o);
                BL[0][0] = r0; BL[0][1] = r2; BL[1][0] = r1; BL[1][1] = r3;
            }
#pragma unroll
            for (int mi = 0; mi < 4; mi++)
#pragma unroll
                for (int ni = 0; ni < 2; ni++) {
                    MMA16(c[mi][ni], A[mi], BH[ni][0], BH[ni][1]);
                    MMA16(c[mi][ni], L[mi], BH[ni][0], BH[ni][1]);
                    MMA16(c[mi][ni], A[mi], BL[ni][0], BL[ni][1]);
                }
        }
        __syncthreads();
    }
#pragma unroll
    for (int mi = 0; mi < 4; mi++)
#pragma unroll
        for (int ni = 0; ni < 2; ni++) {
            int col = n0 + wn + ni * 8 + (lane & 3) * 2;
            float b0 = gb1[col], b1v = gb1[col + 1];
#pragma unroll
            for (int h = 0; h < 2; h++) {
                int r = m0 + wm + mi * 16 + (lane >> 2) + h * 8;
                *(float2*)(g_h1 + (size_t)r * GHID + col) =
                    make_float2(fmaxf(c[mi][ni][2 * h] + b0, 0.f),
                                fmaxf(c[mi][ni][2 * h + 1] + b1v, 0.f));
            }
        }
}

// ----- layer-1 merged GEMM: z=0 -> H=relu(Xg@w1+b1); z=1 -> P=Xg@wp+bp ------
__global__ void __launch_bounds__(256, 2) k_l1(
    const __half* __restrict__ w1t, const __half* __restrict__ wpt,
    const float* __restrict__ b1b, const float* __restrict__ bpb) {
    const int K = DIN, N = HID;
    int t = blockIdx.y;
    if (t >= g_ntiles) return;
    bool isH = (blockIdx.z == 0);
    int e = g_tile_e[t];
    int m0 = g_tile_m0[t];
    int off = g_offsets[e], M = g_offsets[e + 1] - off;
    int n0 = blockIdx.x * 128;
    const __half* A = g_Xg + (size_t)off * K;
    const __half* Wt = (isH ? w1t : wpt) + ((size_t)e * N + n0) * K;
    const float* bias = (isH ? b1b : bpb) + (size_t)e * N + n0;
    __half* C = (isH ? g_H : g_P) + (size_t)off * N;

    extern __shared__ char sm_raw[];
    uint32_t sb = (smem_u32(sm_raw) + 1023u) & ~1023u;
    int tid = threadIdx.x, warp = tid >> 5, lane = tid & 31;
    int wm = (warp & 1) * 64, wn = (warp >> 1) * 32;

    int lrow[4], lch[4];
#pragma unroll
    for (int i = 0; i < 4; i++) { int idx = tid + i * 256; lrow[i] = idx >> 3; lch[i] = idx & 7; }

    float c[4][4][4];
#pragma unroll
    for (int a = 0; a < 4; a++)
#pragma unroll
        for (int b = 0; b < 4; b++)
#pragma unroll
            for (int q = 0; q < 4; q++) c[a][b][q] = 0.f;

    const int nk = K >> 6;
    auto issue = [&](int kt, int s) {
        uint32_t st = sb + (uint32_t)s * 32768;
#pragma unroll
        for (int i = 0; i < 4; i++) {
            int r = lrow[i];
            uint32_t so = swz((uint32_t)(r * 128 + lch[i] * 16));
            CPA(st + so, (const char*)(A + (size_t)(m0 + r) * K + kt * 64 + lch[i] * 8),
                (m0 + r < M) ? 16 : 0);
            CPA(st + 16384 + so, (const char*)(Wt + (size_t)r * K + kt * 64 + lch[i] * 8), 16);
        }
    };
    issue(0, 0); CPCOMMIT();
    for (int kt = 0; kt < nk; kt++) {
        int s = kt & 1;
        if (kt + 1 < nk) { issue(kt + 1, s ^ 1); CPCOMMIT(); CPWAIT(1); }
        else CPWAIT(0);
        __syncthreads();
        uint32_t ab = sb + (uint32_t)s * 32768, bbs = ab + 16384;
#pragma unroll
        for (int ks = 0; ks < 4; ks++) {
            uint32_t Af[4][4], Bf[4][2];
#pragma unroll
            for (int mi = 0; mi < 4; mi++) {
                uint32_t o = swz((uint32_t)((wm + mi * 16 + (lane & 15)) * 128 + ks * 32 + (lane >> 4) * 16));
                LDSM4(Af[mi][0], Af[mi][1], Af[mi][2], Af[mi][3], ab + o);
            }
#pragma unroll
            for (int p = 0; p < 2; p++) {
                uint32_t o = swz((uint32_t)((wn + p * 16 + (lane & 15)) * 128 + ks * 32 + (lane >> 4) * 16));
                uint32_t r0, r1, r2, r3;
                LDSM4(r0, r1, r2, r3, bbs + o);
                Bf[2 * p][0] = r0; Bf[2 * p][1] = r2; Bf[2 * p + 1][0] = r1; Bf[2 * p + 1][1] = r3;
            }
#pragma unroll
            for (int mi = 0; mi < 4; mi++)
#pragma unroll
                for (int ni = 0; ni < 4; ni++)
                    MMA16(c[mi][ni], Af[mi], Bf[ni][0], Bf[ni][1]);
        }
        __syncthreads();
    }
#pragma unroll
    for (int mi = 0; mi < 4; mi++)
#pragma unroll
        for (int ni = 0; ni < 4; ni++) {
            int col = wn + ni * 8 + (lane & 3) * 2;
            float b0 = bias[col], b1v = bias[col + 1];
#pragma unroll
            for (int h = 0; h < 2; h++) {
                int r = m0 + wm + mi * 16 + (lane >> 2) + h * 8;
                if (r < M) {
                    float v0 = c[mi][ni][2 * h] + b0, v1 = c[mi][ni][2 * h + 1] + b1v;
                    if (isH) { v0 = fmaxf(v0, 0.f); v1 = fmaxf(v1, 0.f); }
                    *(__half2*)(C + (size_t)r * N + n0 + col) =
                        __halves2half2(__float2half_rn(v0), __float2half_rn(v1));
                }
            }
        }
}

// ------- routed fp16 GEMM (128x128, 2-stage, occ2), tile-list grid ---------
template <bool RELU, bool HAS_EXTRA, bool OUT_HALF>
__global__ void __launch_bounds__(256, 2) k_std16(
    const __half* __restrict__ Ab, const __half* __restrict__ Wb,
    const float* __restrict__ biasb, const __half* __restrict__ extrab,
    void* __restrict__ Cb, int N, int K) {
    int t = blockIdx.y;
    if (t >= g_ntiles) return;
    int e = g_tile_e[t];
    int m0 = g_tile_m0[t];
    int off = g_offsets[e], M = g_offsets[e + 1] - off;
    int n0 = blockIdx.x * 128;
    const __half* A = Ab + (size_t)off * K;
    const __half* Wt = Wb + ((size_t)e * N + n0) * K;
    const float* bias = biasb + (size_t)e * N + n0;

    extern __shared__ char sm_raw[];
    uint32_t sb = (smem_u32(sm_raw) + 1023u) & ~1023u;
    int tid = threadIdx.x, warp = tid >> 5, lane = tid & 31;
    int wm = (warp & 1) * 64, wn = (warp >> 1) * 32;

    int lrow[4], lch[4];
#pragma unroll
    for (int i = 0; i < 4; i++) { int idx = tid + i * 256; lrow[i] = idx >> 3; lch[i] = idx & 7; }

    float c[4][4][4];
#pragma unroll
    for (int a = 0; a < 4; a++)
#pragma unroll
        for (int b = 0; b < 4; b++)
#pragma unroll
            for (int q = 0; q < 4; q++) c[a][b][q] = 0.f;

    const int nk = K >> 6;
    auto issue = [&](int kt, int s) {
        uint32_t st = sb + (uint32_t)s * 32768;
#pragma unroll
        for (int i = 0; i < 4; i++) {
            int r = lrow[i];
            uint32_t so = swz((uint32_t)(r * 128 + lch[i] * 16));
            CPA(st + so, (const char*)(A + (size_t)(m0 + r) * K + kt * 64 + lch[i] * 8),
                (m0 + r < M) ? 16 : 0);
            CPA(st + 16384 + so, (const char*)(Wt + (size_t)r * K + kt * 64 + lch[i] * 8), 16);
        }
    };
    issue(0, 0); CPCOMMIT();
    for (int kt = 0; kt < nk; kt++) {
        int s = kt & 1;
        if (kt + 1 < nk) { issue(kt + 1, s ^ 1); CPCOMMIT(); CPWAIT(1); }
        else CPWAIT(0);
        __syncthreads();
        uint32_t ab = sb + (uint32_t)s * 32768, bbs = ab + 16384;
#pragma unroll
        for (int ks = 0; ks < 4; ks++) {
            uint32_t Af[4][4], Bf[4][2];
#pragma unroll
            for (int mi = 0; mi < 4; mi++) {
                uint32_t o = swz((uint32_t)((wm + mi * 16 + (lane & 15)) * 128 + ks * 32 + (lane >> 4) * 16));
                LDSM4(Af[mi][0], Af[mi][1], Af[mi][2], Af[mi][3], ab + o);
            }
#pragma unroll
            for (int p = 0; p < 2; p++) {
                uint32_t o = swz((uint32_t)((wn + p * 16 + (lane & 15)) * 128 + ks * 32 + (lane >> 4) * 16));
                uint32_t r0, r1, r2, r3;
                LDSM4(r0, r1, r2, r3, bbs + o);
                Bf[2 * p][0] = r0; Bf[2 * p][1] = r2; Bf[2 * p + 1][0] = r1; Bf[2 * p + 1][1] = r3;
            }
#pragma unroll
            for (int mi = 0; mi < 4; mi++)
#pragma unroll
                for (int ni = 0; ni < 4; ni++)
                    MMA16(c[mi][ni], Af[mi], Bf[ni][0], Bf[ni][1]);
        }
        __syncthreads();
    }
#pragma unroll
    for (int mi = 0; mi < 4; mi++)
#pragma unroll
        for (int ni = 0; ni < 4; ni++) {
            int col = wn + ni * 8 + (lane & 3) * 2;
            float b0 = bias[col], b1v = bias[col + 1];
#pragma unroll
            for (int h = 0; h < 2; h++) {
                int r = m0 + wm + mi * 16 + (lane >> 2) + h * 8;
                if (r < M) {
                    float v0 = c[mi][ni][2 * h] + b0, v1 = c[mi][ni][2 * h + 1] + b1v;
                    if (HAS_EXTRA) {
                        float2 ex = __half22float2(
                            *(const __half2*)(extrab + ((size_t)off + r) * N + n0 + col));
                        v0 += ex.x; v1 += ex.y;
                    }
                    if (RELU) { v0 = fmaxf(v0, 0.f); v1 = fmaxf(v1, 0.f); }
                    if (OUT_HALF)
                        *(__half2*)((__half*)Cb + ((size_t)off + r) * N + n0 + col) =
                            __halves2half2(__float2half_rn(v0), __float2half_rn(v1));
                    else
                        *(float2*)((float*)Cb + ((size_t)off + r) * N + n0 + col) =
                            make_float2(v0, v1);
                }
            }
        }
}

// ------------------------- routing / small kernels --------------------------
__global__ void k_gating2(const float* __restrict__ gw2, const float* __restrict__ gb2) {
    int warp_g = (blockIdx.x * blockDim.x + threadIdx.x) >> 5;
    if (warp_g >= NB) return;
    int lane = threadIdx.x & 31;
    const float* hrow = g_h1 + (size_t)warp_g * GHID;
    float acc[NE];
#pragma unroll
    for (int e = 0; e < NE; e++) acc[e] = 0.f;
    for (int g = lane; g < GHID; g += 32) {
        float hv = hrow[g];
        const float* wr = gw2 + (size_t)g * NE;
#pragma unroll
        for (int e = 0; e < NE; e++) acc[e] = fmaf(hv, wr[e], acc[e]);
    }
#pragma unroll
    for (int e = 0; e < NE; e++)
#pragma unroll
        for (int s = 16; s > 0; s >>= 1) acc[e] += __shfl_xor_sync(0xffffffffu, acc[e], s);
    if (lane == 0) {
#pragma unroll
        for (int e = 0; e < NE; e++) acc[e] += gb2[e];
        int i1 = 0;
#pragma unroll
        for (int e = 1; e < NE; e++) if (acc[e] > acc[i1]) i1 = e;
        int i2 = (i1 == 0) ? 1 : 0;
#pragma unroll
        for (int e = 0; e < NE; e++) if (e != i1 && acc[e] > acc[i2]) i2 = e;
        float e2 = expf(acc[i2] - acc[i1]);
        float inv = 1.f / (1.f + e2);
        g_topk_e[2 * warp_g] = i1;   g_topk_e[2 * warp_g + 1] = i2;
        g_topk_w[2 * warp_g] = inv;  g_topk_w[2 * warp_g + 1] = e2 * inv;
        atomicAdd(&g_counts[i1], 1); atomicAdd(&g_counts[i2], 1);
    }
}

__global__ void k_offsets() {
    if (threadIdx.x == 0) {
        int acc = 0;
#pragma unroll
        for (int e = 0; e < NE; e++) { g_offsets[e] = acc; g_cursor[e] = acc; acc += g_counts[e]; }
        g_offsets[NE] = acc;
        int nt = 0;
        for (int e = 0; e < NE; e++) {
            int cnt = g_counts[e];
            for (int m0 = 0; m0 < cnt; m0 += 128) {
                g_tile_e[nt] = e;
                g_tile_m0[nt] = m0;
                nt++;
            }
        }
        g_ntiles = nt;
    }
}

__global__ void k_fill() {
    int t = blockIdx.x * blockDim.x + threadIdx.x;
    if (t >= NB) return;
#pragma unroll
    for (int k = 0; k < 2; k++) {
        int e = g_topk_e[2 * t + k];
        int pos = atomicAdd(&g_cursor[e], 1);
        g_slot_token[pos] = t;
        g_token_slot[2 * t + k] = pos;
    }
}

__global__ void k_gather(const float* __restrict__ x) {
    int s = blockIdx.x;
    int tok = g_slot_token[s];
    float4 v = ((const float4*)(x + (size_t)tok * DIN))[threadIdx.x];
    __half2* dst = (__half2*)(g_Xg + (size_t)s * DIN);
    dst[2 * threadIdx.x]     = __halves2half2(__float2half_rn(v.x), __float2half_rn(v.y));
    dst[2 * threadIdx.x + 1] = __halves2half2(__float2half_rn(v.z), __float2half_rn(v.w));
}

__global__ void k_combine(float* __restrict__ out) {
    int t = blockIdx.x, i = threadIdx.x;
    int s0 = g_token_slot[2 * t], s1 = g_token_slot[2 * t + 1];
    float w0 = g_topk_w[2 * t], w1 = g_topk_w[2 * t + 1];
    float4 y0 = ((const float4*)(g_Y + (size_t)s0 * DOUT))[i];
    float4 y1 = ((const float4*)(g_Y + (size_t)s1 * DOUT))[i];
    float4 o;
    o.x = w0 * y0.x + w1 * y1.x;  o.y = w0 * y0.y + w1 * y1.y;
    o.z = w0 * y0.z + w1 * y1.z;  o.w = w0 * y0.w + w1 * y1.w;
    ((float4*)out)[(size_t)t * (DOUT / 4) + i] = o;
}

// ------------------------------- launch -------------------------------------
extern "C" void kernel_launch(void* const* d_in, const int* in_sizes, int n_in,
                              void* d_out, int out_size) {
    const float* x   = (const float*)d_in[0];
    const float* w1  = (const float*)d_in[1];
    const float* b1  = (const float*)d_in[2];
    const float* w2  = (const float*)d_in[3];
    const float* b2  = (const float*)d_in[4];
    const float* w3  = (const float*)d_in[5];
    const float* b3  = (const float*)d_in[6];
    const float* wp  = (const float*)d_in[7];
    const float* bp  = (const float*)d_in[8];
    const float* gw1 = (const float*)d_in[9];
    const float* gb1 = (const float*)d_in[10];
    const float* gw2 = (const float*)d_in[11];
    const float* gb2 = (const float*)d_in[12];
    float* out = (float*)d_out;

    __half *w1t, *wpt, *w2t, *w3t, *gwh, *gwl, *H, *O, *P;
    float *Y;
    cudaGetSymbolAddress((void**)&w1t, g_w1t);
    cudaGetSymbolAddress((void**)&wpt, g_wpt);
    cudaGetSymbolAddress((void**)&w2t, g_w2t);
    cudaGetSymbolAddress((void**)&w3t, g_w3t);
    cudaGetSymbolAddress((void**)&gwh, g_gwh);
    cudaGetSymbolAddress((void**)&gwl, g_gwl);
    cudaGetSymbolAddress((void**)&H,   g_H);
    cudaGetSymbolAddress((void**)&O,   g_O);
    cudaGetSymbolAddress((void**)&P,   g_P);
    cudaGetSymbolAddress((void**)&Y,   g_Y);

    auto* T2 = k_std16<true,  true,  true>;    // O = relu(H@w2 + P + b2)
    auto* T3 = k_std16<false, false, false>;   // Y = O@w3 + b3
    const int SM_STD  = 2 * 32768;
    const int SM_GATE = 2 * 49152;
    cudaFuncSetAttribute(k_l1, cudaFuncAttributeMaxDynamicSharedMemorySize, SM_STD);
    cudaFuncSetAttribute(T2, cudaFuncAttributeMaxDynamicSharedMemorySize, SM_STD);
    cudaFuncSetAttribute(T3, cudaFuncAttributeMaxDynamicSharedMemorySize, SM_STD);
    cudaFuncSetAttribute(k_gate16, cudaFuncAttributeMaxDynamicSharedMemorySize, SM_GATE);

    static cudaStream_t s_aux = nullptr;
    static cudaEvent_t evFork = nullptr, evW1 = nullptr, evW2 = nullptr;
    if (s_aux == nullptr) {
        cudaStreamCreateWithFlags(&s_aux, cudaStreamNonBlocking);
        cudaEventCreateWithFlags(&evFork, cudaEventDisableTiming);
        cudaEventCreateWithFlags(&evW1, cudaEventDisableTiming);
        cudaEventCreateWithFlags(&evW2, cudaEventDisableTiming);
    }

    // Fork: weight transposes overlap the gating chain (fully hidden).
    cudaEventRecord(evFork, 0);
    cudaStreamWaitEvent(s_aux, evFork, 0);
    k_t16<false><<<dim3(HID / 32, DIN / 64, NE), 256, 0, s_aux>>>(w1, w1t, nullptr, DIN, HID);
    k_t16<false><<<dim3(HID / 32, DIN / 64, NE), 256, 0, s_aux>>>(wp, wpt, nullptr, DIN, HID);
    cudaEventRecord(evW1, s_aux);
    k_t16<false><<<dim3(HID / 32, HID / 64, NE), 256, 0, s_aux>>>(w2, w2t, nullptr, HID, HID);
    k_t16<false><<<dim3(DOUT / 32, HID / 64, NE), 256, 0, s_aux>>>(w3, w3t, nullptr, HID, DOUT);
    cudaEventRecord(evW2, s_aux);

    // Gating chain on the main stream.
    k_split_x<<<(NB * DIN / 4) / 256, 256>>>(x);
    k_t16<true><<<dim3(GHID / 32, DIN / 64, 1), 256>>>(gw1, gwh, gwl, DIN, GHID);
    k_gate16<<<dim3(GHID / 64, NB / 128), 256, SM_GATE>>>(gb1);
    k_gating2<<<NB / 8, 256>>>(gw2, gb2);
    k_offsets<<<1, 32>>>();
    k_fill<<<NB / 256, 256>>>();
    k_gather<<<NSLOT, 256>>>(x);

    // Expert GEMMs: merged layer-1 (H and P in one launch), then T2, T3.
    cudaStreamWaitEvent(0, evW1, 0);
    k_l1<<<dim3(HID / 128, MAXT, 2), 256, SM_STD>>>(w1t, wpt, b1, bp);
    cudaStreamWaitEvent(0, evW2, 0);
    T2<<<dim3(HID / 128, MAXT), 256, SM_STD>>>(H, w2t, b2, P, O, HID, HID);
    T3<<<dim3(DOUT / 128, MAXT), 256, SM_STD>>>(O, w3t, b3, nullptr, Y, DOUT, HID);
    k_combine<<<NB, 256>>>(out);
}